// round 5
// baseline (speedup 1.0000x reference)
#include <cuda_runtime.h>
#include <cuda_bf16.h>
#include <math.h>
#include <stdint.h>

#define Bsz 4
#define SEQ 4096
#define WID 768
#define NH  12
#define MBm 16
#define NBt 256           // SEQ / MBm
#define EPSV 1e-6f
#define MTOT (Bsz*SEQ)    // 16384
#define WW   (WID*WID)

// ------------------------- scratch (device globals) -------------------------
__device__ __align__(16) float g_xqk [Bsz*SEQ*WID];
__device__ __align__(16) float g_xv  [Bsz*SEQ*WID];
__device__ __align__(16) float g_gate[Bsz*SEQ*WID];
__device__ __align__(16) float g_ttt [Bsz*SEQ*WID];
__device__ __align__(16) float g_lr  [Bsz*NH*SEQ];
__device__ __align__(16) __nv_bfloat16 g_hh[Bsz*SEQ*WID];
__device__ __align__(16) __nv_bfloat16 g_hl[Bsz*SEQ*WID];
__device__ __align__(16) __nv_bfloat16 g_th[Bsz*SEQ*WID];
__device__ __align__(16) __nv_bfloat16 g_tl[Bsz*SEQ*WID];
// [0,3WW): hi of {wq,wv,wg} stacked; [3WW,6WW): lo stacked; [6WW): wo hi; [7WW): wo lo
__device__ __align__(16) __nv_bfloat16 g_wt[8*WW];

// ------------------------- helpers -------------------------
__device__ __forceinline__ uint32_t smem_u32(const void* p) {
    uint32_t a;
    asm("{ .reg .u64 t; cvta.to.shared.u64 t, %1; cvt.u32.u64 %0, t; }" : "=r"(a) : "l"(p));
    return a;
}
__device__ __forceinline__ float wred(float v) {
#pragma unroll
    for (int o = 16; o; o >>= 1) v += __shfl_xor_sync(0xffffffffu, v, o);
    return v;
}
__device__ __forceinline__ float hred(float v) {
#pragma unroll
    for (int o = 8; o; o >>= 1) v += __shfl_xor_sync(0xffffffffu, v, o);
    return v;
}
__device__ __forceinline__ unsigned long long pk2(float lo, float hi) {
    unsigned long long r;
    asm("mov.b64 %0, {%1, %2};" : "=l"(r) : "f"(lo), "f"(hi));
    return r;
}
__device__ __forceinline__ void fma2(unsigned long long& acc,
                                     unsigned long long a, unsigned long long b) {
    asm("fma.rn.f32x2 %0, %1, %2, %0;" : "+l"(acc) : "l"(a), "l"(b));
}
__device__ __forceinline__ float2 up2(unsigned long long v) {
    float lo, hi;
    asm("mov.b64 {%0, %1}, %2;" : "=f"(lo), "=f"(hi) : "l"(v));
    return make_float2(lo, hi);
}
__device__ __forceinline__ void cpa16(uint32_t saddr, const void* g) {
    asm volatile("cp.async.cg.shared.global [%0], [%1], 16;" :: "r"(saddr), "l"(g) : "memory");
}
__device__ __forceinline__ void cpa_commit() {
    asm volatile("cp.async.commit_group;" ::: "memory");
}
__device__ __forceinline__ void ldsm4(uint32_t& r0, uint32_t& r1, uint32_t& r2, uint32_t& r3, uint32_t a) {
    asm volatile("ldmatrix.sync.aligned.m8n8.x4.shared.b16 {%0,%1,%2,%3}, [%4];"
                 : "=r"(r0), "=r"(r1), "=r"(r2), "=r"(r3) : "r"(a));
}
__device__ __forceinline__ void mma16816(float* c, const uint32_t* a, const uint32_t* b) {
    asm volatile("mma.sync.aligned.m16n8k16.row.col.f32.bf16.bf16.f32 "
                 "{%0,%1,%2,%3}, {%4,%5,%6,%7}, {%8,%9}, {%0,%1,%2,%3};"
                 : "+f"(c[0]), "+f"(c[1]), "+f"(c[2]), "+f"(c[3])
                 : "r"(a[0]), "r"(a[1]), "r"(a[2]), "r"(a[3]), "r"(b[0]), "r"(b[1]));
}

// --------- prep kernel: lr logits (blocks [0,2048)) + weight cvt (rest) -----
__global__ __launch_bounds__(256) void prep_kernel(
    const float* __restrict__ hidden, const float* __restrict__ lrk,
    const float* __restrict__ lrb,
    const float* __restrict__ w0, const float* __restrict__ w1,
    const float* __restrict__ w2, const float* __restrict__ w3)
{
    __shared__ float sk[NH * WID];       // lr branch (36KB)
    __shared__ float tile[32][33];       // cvt branch
    const int tid = threadIdx.x;

    if (blockIdx.x < 2048) {
        for (int i = tid; i < NH * WID; i += 256) sk[i] = lrk[i];
        __syncthreads();
        const int gw = blockIdx.x * 8 + (tid >> 5);
        const int lane = tid & 31;
        const float* hrow = hidden + (size_t)gw * WID;
        float acc[NH];
#pragma unroll
        for (int h = 0; h < NH; h++) acc[h] = 0.f;
        for (int w = lane; w < WID; w += 32) {
            float hv = hrow[w];
#pragma unroll
            for (int h = 0; h < NH; h++) acc[h] += hv * sk[h * WID + w];
        }
        const int b = gw >> 12, n = gw & (SEQ - 1);
#pragma unroll
        for (int h = 0; h < NH; h++) {
            float v = wred(acc[h]);
            if (lane == 0) {
                float x = v + lrb[h];
                g_lr[(size_t)(b * NH + h) * SEQ + n] = (1.f / (1.f + expf(-x))) * (1.f / 64.f);
            }
        }
    } else {
        const int bi = blockIdx.x - 2048;
        const int z = bi / 576;
        const int rem = bi % 576;
        const float* w = (z == 0) ? w0 : (z == 1) ? w1 : (z == 2) ? w2 : w3;
        __nv_bfloat16* th = g_wt + ((z < 3) ? (size_t)z * WW : (size_t)6 * WW);
        __nv_bfloat16* tl = g_wt + ((z < 3) ? (size_t)(3 + z) * WW : (size_t)7 * WW);
        const int bx = (rem % 24) * 32;
        const int by = (rem / 24) * 32;
        const int x = tid & 31, y = tid >> 5;
#pragma unroll
        for (int j = 0; j < 4; j++)
            tile[y + j * 8][x] = w[(size_t)(by + y + j * 8) * WID + bx + x];
        __syncthreads();
#pragma unroll
        for (int j = 0; j < 4; j++) {
            float v = tile[x][y + j * 8];
            __nv_bfloat16 hh = __float2bfloat16(v);
            size_t o = (size_t)(bx + y + j * 8) * WID + by + x;
            th[o] = hh;
            tl[o] = __float2bfloat16(v - __bfloat162float(hh));
        }
    }
}

// ------------------------- fp32 -> bf16 hi/lo split --------------------------
__global__ __launch_bounds__(256) void cvt_hilo_kernel(
    const float* __restrict__ x, __nv_bfloat16* __restrict__ hi,
    __nv_bfloat16* __restrict__ lo, int n4)
{
    int i = blockIdx.x * 256 + threadIdx.x;
    if (i >= n4) return;
    float4 v = ((const float4*)x)[i];
    __nv_bfloat16 h0 = __float2bfloat16(v.x), h1 = __float2bfloat16(v.y);
    __nv_bfloat16 h2 = __float2bfloat16(v.z), h3 = __float2bfloat16(v.w);
    __nv_bfloat16 l0 = __float2bfloat16(v.x - __bfloat162float(h0));
    __nv_bfloat16 l1 = __float2bfloat16(v.y - __bfloat162float(h1));
    __nv_bfloat16 l2 = __float2bfloat16(v.z - __bfloat162float(h2));
    __nv_bfloat16 l3 = __float2bfloat16(v.w - __bfloat162float(h3));
    __nv_bfloat162 ph0(h0, h1), ph1(h2, h3), pl0(l0, l1), pl1(l2, l3);
    ((uint2*)hi)[i] = make_uint2(*(unsigned*)&ph0, *(unsigned*)&ph1);
    ((uint2*)lo)[i] = make_uint2(*(unsigned*)&pl0, *(unsigned*)&pl1);
}

// ------------------------- bf16-split GEMM via mma.sync ----------------------
#define TSTRIDE 40
#define TILEB  (128*TSTRIDE*2)
#define STAGEB (4*TILEB)

__global__ __launch_bounds__(256) void mma_gemm_kernel(
    const __nv_bfloat16* __restrict__ Ah, const __nv_bfloat16* __restrict__ Al,
    const __nv_bfloat16* __restrict__ Bh, const __nv_bfloat16* __restrict__ Bl,
    float* __restrict__ C0, float* __restrict__ C1, float* __restrict__ C2)
{
    extern __shared__ char smem[];
    const uint32_t sb = smem_u32(smem);
    const int tid = threadIdx.x, wid = tid >> 5, lane = tid & 31;
    const int bm = blockIdx.y * 128;
    const int bn = blockIdx.x * 128;
    const int buf = blockIdx.x / 6;
    const int coloff = (blockIdx.x % 6) * 128;
    float* C = (buf == 0) ? C0 : (buf == 1) ? C1 : C2;
    const int warpM = wid & 3, warpN = wid >> 2;

    const __nv_bfloat16* srcs[4] = {
        Ah + (size_t)bm * WID, Al + (size_t)bm * WID,
        Bh + (size_t)bn * WID, Bl + (size_t)bn * WID };

    auto load_stage = [&](int st, int k0) {
#pragma unroll
        for (int t = 0; t < 4; t++) {
#pragma unroll
            for (int rep = 0; rep < 2; rep++) {
                int li = tid + rep * 256;
                int row = li >> 2, cc = li & 3;
                const void* g = srcs[t] + (size_t)row * WID + k0 + cc * 8;
                uint32_t sa = sb + st * STAGEB + t * TILEB + row * (TSTRIDE * 2) + cc * 16;
                cpa16(sa, g);
            }
        }
        cpa_commit();
    };

    float acc[2][8][4];
#pragma unroll
    for (int i = 0; i < 2; i++)
#pragma unroll
        for (int j = 0; j < 8; j++)
#pragma unroll
            for (int k = 0; k < 4; k++) acc[i][j][k] = 0.f;

    load_stage(0, 0);

    const int NK = WID / 32;
    for (int kt = 0; kt < NK; kt++) {
        if (kt + 1 < NK) load_stage((kt + 1) & 1, (kt + 1) * 32);
        if (kt + 1 < NK) asm volatile("cp.async.wait_group 1;" ::: "memory");
        else             asm volatile("cp.async.wait_group 0;" ::: "memory");
        __syncthreads();

        const uint32_t base = sb + (kt & 1) * STAGEB;
        const int lrow = lane & 15;
        const int lcol = (lane & 16) ? 8 : 0;

#pragma unroll
        for (int kk = 0; kk < 2; kk++) {
            const int kb = kk * 16;
            uint32_t ah[2][4], al[2][4], bh[8][2], bl[8][2];
#pragma unroll
            for (int mt = 0; mt < 2; mt++) {
                uint32_t off = (uint32_t)((warpM * 32 + mt * 16 + lrow) * TSTRIDE + kb + lcol) * 2;
                ldsm4(ah[mt][0], ah[mt][1], ah[mt][2], ah[mt][3], base + 0 * TILEB + off);
                ldsm4(al[mt][0], al[mt][1], al[mt][2], al[mt][3], base + 1 * TILEB + off);
            }
#pragma unroll
            for (int ng = 0; ng < 4; ng++) {
                uint32_t off = (uint32_t)((warpN * 64 + ng * 16 + lrow) * TSTRIDE + kb + lcol) * 2;
                uint32_t r0, r1, r2, r3;
                ldsm4(r0, r1, r2, r3, base + 2 * TILEB + off);
                bh[ng * 2][0] = r0; bh[ng * 2 + 1][0] = r1;
                bh[ng * 2][1] = r2; bh[ng * 2 + 1][1] = r3;
                ldsm4(r0, r1, r2, r3, base + 3 * TILEB + off);
                bl[ng * 2][0] = r0; bl[ng * 2 + 1][0] = r1;
                bl[ng * 2][1] = r2; bl[ng * 2 + 1][1] = r3;
            }
#pragma unroll
            for (int mt = 0; mt < 2; mt++)
#pragma unroll
                for (int nt = 0; nt < 8; nt++) {
                    mma16816(acc[mt][nt], ah[mt], bh[nt]);
                    mma16816(acc[mt][nt], ah[mt], bl[nt]);
                    mma16816(acc[mt][nt], al[mt], bh[nt]);
                }
        }
        __syncthreads();
    }

    const int r0 = bm + warpM * 32 + (lane >> 2);
    const int cb = coloff + warpN * 64 + 2 * (lane & 3);
#pragma unroll
    for (int mt = 0; mt < 2; mt++)
#pragma unroll
        for (int nt = 0; nt < 8; nt++) {
            int row = r0 + mt * 16, col = cb + nt * 8;
            *(float2*)(C + (size_t)row * WID + col) = make_float2(acc[mt][nt][0], acc[mt][nt][1]);
            *(float2*)(C + (size_t)(row + 8) * WID + col) = make_float2(acc[mt][nt][2], acc[mt][nt][3]);
        }
}

// ------------------------- TTT scan (512 threads, fused conv+rope) ----------
// Team 0 = tid<256 (layout r=tid>>4, cg=tid&15): conv/rope, LN phases, output.
// Team 1 = tid>=256: lr staging, Cf matrix, W1/b1 update.
// GEMM phase (all 512): warp w: s=w&1 (k-half), rows {2*(w>>1), 2*(w>>1)+1}.
__global__ __launch_bounds__(512) void ttt_scan_kernel(
    const float* __restrict__ W1in, const float* __restrict__ b1in,
    const float* __restrict__ gin,  const float* __restrict__ bbin,
    const float* __restrict__ lti,
    const float* __restrict__ cqk, const float* __restrict__ cqb,
    const float* __restrict__ ckk, const float* __restrict__ ckb)
{
    __shared__ float W1s[64 * 64];
    __shared__ float b1s[64];
    __shared__ float sXQ[16 * 68], sXK[16 * 68], sG[16 * 68];
    __shared__ float sPK[2 * 16 * 68], sPQ[2 * 16 * 68];
    __shared__ float Cf[256];
    __shared__ float lr[16], lrw[16], toki[16];

    const int tid = threadIdx.x;
    const int bh = blockIdx.x;
    const int b = bh / NH, h = bh % NH;
    const bool t0 = (tid < 256);
    const int t = t0 ? tid : tid - 256;

    for (int i = tid; i < 4096; i += 512) W1s[i] = W1in[h * 4096 + i];
    if (tid < 64) b1s[tid] = b1in[h * 64 + tid];
    if (tid < 16) toki[tid] = fmaxf(1.f / (float)(tid + 1) + lti[tid], 0.f);

    const int r  = t >> 4;
    const int cg = t & 15;
    const int c0 = cg * 4;
    // GEMM layout
    const int wA  = tid >> 5;
    const int sA  = wA & 1;
    const int rA  = (wA >> 1) * 2 + ((tid >> 4) & 1);
    const int c0A = (tid & 15) * 4;

    const size_t gb2 = (size_t)b * SEQ * WID + h * 64 + c0;
    const float* lrp = g_lr + (size_t)bh * SEQ;

    // team-0 constants: conv weights, biases, rope trig, LN params
    float4 wq0, wq1, wq2, wq3, wk0, wk1, wk2, wk3, qb4, kb4;
    float cs0 = 0.f, sn0 = 0.f, cs1 = 0.f, sn1 = 0.f;
    float gv0 = 0.f, gv1 = 0.f, gv2 = 0.f, gv3 = 0.f;
    float bv0 = 0.f, bv1 = 0.f, bv2 = 0.f, bv3 = 0.f;
    if (t0) {
        wq0 = *(const float4*)(cqk + 0 * WID + h * 64 + c0);
        wq1 = *(const float4*)(cqk + 1 * WID + h * 64 + c0);
        wq2 = *(const float4*)(cqk + 2 * WID + h * 64 + c0);
        wq3 = *(const float4*)(cqk + 3 * WID + h * 64 + c0);
        wk0 = *(const float4*)(ckk + 0 * WID + h * 64 + c0);
        wk1 = *(const float4*)(ckk + 1 * WID + h * 64 + c0);
        wk2 = *(const float4*)(ckk + 2 * WID + h * 64 + c0);
        wk3 = *(const float4*)(ckk + 3 * WID + h * 64 + c0);
        qb4 = *(const float4*)(cqb + h * 64 + c0);
        kb4 = *(const float4*)(ckb + h * 64 + c0);
        int j0 = c0 >> 1;
        float f0 = expf(-9.210340371976184f * (float)j0 * (1.f / 32.f));
        float f1 = expf(-9.210340371976184f * (float)(j0 + 1) * (1.f / 32.f));
        cs0 = cosf((float)r * f0); sn0 = sinf((float)r * f0);
        cs1 = cosf((float)r * f1); sn1 = sinf((float)r * f1);
        gv0 = gin[h * 64 + c0];     gv1 = gin[h * 64 + c0 + 1];
        gv2 = gin[h * 64 + c0 + 2]; gv3 = gin[h * 64 + c0 + 3];
        bv0 = bbin[h * 64 + c0];     bv1 = bbin[h * 64 + c0 + 1];
        bv2 = bbin[h * 64 + c0 + 2]; bv3 = bbin[h * 64 + c0 + 3];
    }
    __syncthreads();
    const float tokir  = toki[r];
    const float toki15 = toki[15];

    // prologue prefetch (tile nb=0)
    float4 x0n = make_float4(0, 0, 0, 0), x1n = x0n, x2n = x0n, x3n = x0n, v4n = x0n;
    float lrn = 0.f;
    if (t0) {
        if (r >= 3) x0n = *(const float4*)(g_xqk + gb2 + (size_t)(r - 3) * WID);
        if (r >= 2) x1n = *(const float4*)(g_xqk + gb2 + (size_t)(r - 2) * WID);
        if (r >= 1) x2n = *(const float4*)(g_xqk + gb2 + (size_t)(r - 1) * WID);
        x3n = *(const float4*)(g_xqk + gb2 + (size_t)r * WID);
        v4n = *(const float4*)(g_xv + gb2 + (size_t)r * WID);
    } else if (t < 16) {
        lrn = lrp[t];
    }

    float4 q4c = make_float4(0, 0, 0, 0), t4c = q4c;

    for (int nb = 0; nb < NBt; nb++) {
        __syncthreads();                                   // (A)
        if (t0) {
            // conv (4-tap causal) then rope; pos = r
            float4 q, k;
            q.x = qb4.x + x0n.x * wq0.x + x1n.x * wq1.x + x2n.x * wq2.x + x3n.x * wq3.x;
            q.y = qb4.y + x0n.y * wq0.y + x1n.y * wq1.y + x2n.y * wq2.y + x3n.y * wq3.y;
            q.z = qb4.z + x0n.z * wq0.z + x1n.z * wq1.z + x2n.z * wq2.z + x3n.z * wq3.z;
            q.w = qb4.w + x0n.w * wq0.w + x1n.w * wq1.w + x2n.w * wq2.w + x3n.w * wq3.w;
            k.x = kb4.x + x0n.x * wk0.x + x1n.x * wk1.x + x2n.x * wk2.x + x3n.x * wk3.x;
            k.y = kb4.y + x0n.y * wk0.y + x1n.y * wk1.y + x2n.y * wk2.y + x3n.y * wk3.y;
            k.z = kb4.z + x0n.z * wk0.z + x1n.z * wk1.z + x2n.z * wk2.z + x3n.z * wk3.z;
            k.w = kb4.w + x0n.w * wk0.w + x1n.w * wk1.w + x2n.w * wk2.w + x3n.w * wk3.w;
            float4 qr, kr;
            qr.x = q.x * cs0 - q.y * sn0; qr.y = q.x * sn0 + q.y * cs0;
            qr.z = q.z * cs1 - q.w * sn1; qr.w = q.z * sn1 + q.w * cs1;
            kr.x = k.x * cs0 - k.y * sn0; kr.y = k.x * sn0 + k.y * cs0;
            kr.z = k.z * cs1 - k.w * sn1; kr.w = k.z * sn1 + k.w * cs1;
            *(float4*)(sXQ + r * 68 + c0) = qr;
            *(float4*)(sXK + r * 68 + c0) = kr;
            q4c = qr;
            t4c = make_float4(v4n.x - kr.x, v4n.y - kr.y, v4n.z - kr.z, v4n.w - kr.w);
        } else if (t < 16) {
            lr[t] = lrn; lrw[t] = toki15 * lrn;
        }
        __syncthreads();                                   // (B)

        // prefetch next tile
        if (nb + 1 < NBt) {
            if (t0) {
                const size_t rb = gb2 + (size_t)((nb + 1) * MBm + r - 3) * WID;
                x0n = *(const float4*)(g_xqk + rb);
                x1n = *(const float4*)(g_xqk + rb + WID);
                x2n = *(const float4*)(g_xqk + rb + 2 * WID);
                x3n = *(const float4*)(g_xqk + rb + 3 * WID);
                v4n = *(const float4*)(g_xv + rb + 3 * WID);
            } else if (t < 16) {
                lrn = lrp[(nb + 1) * MBm + t];
            }
        }

        // ---- GEMM phase (all 512 threads): partial Z1/ZQ over k-half sA ----
        {
            unsigned long long aK0, aK1, aQ0, aQ1;
            if (sA == 0) {
                aK0 = pk2(b1s[c0A], b1s[c0A + 1]);
                aK1 = pk2(b1s[c0A + 2], b1s[c0A + 3]);
            } else { aK0 = 0ULL; aK1 = 0ULL; }
            aQ0 = aK0; aQ1 = aK1;
            const int kb0 = sA * 32;
#pragma unroll 8
            for (int j = 0; j < 32; j++) {
                int k = kb0 + j;
                float xk = sXK[rA * 68 + k];
                float xq = sXQ[rA * 68 + k];
                ulonglong2 w2 = *(const ulonglong2*)(W1s + k * 64 + c0A);
                unsigned long long pkk = pk2(xk, xk), pq = pk2(xq, xq);
                fma2(aK0, pkk, w2.x); fma2(aK1, pkk, w2.y);
                fma2(aQ0, pq,  w2.x); fma2(aQ1, pq,  w2.y);
            }
            float2 a = up2(aK0), bb2 = up2(aK1);
            *(float4*)(sPK + sA * 1088 + rA * 68 + c0A) = make_float4(a.x, a.y, bb2.x, bb2.y);
            float2 c = up2(aQ0), d = up2(aQ1);
            *(float4*)(sPQ + sA * 1088 + rA * 68 + c0A) = make_float4(c.x, c.y, d.x, d.y);
        }
        __syncthreads();                                   // (B2)

        if (t0) {
            // LN-fused-L2-bwd on Z1 = sPK[0]+sPK[1]
            float4 zA = *(const float4*)(sPK + r * 68 + c0);
            float4 zB = *(const float4*)(sPK + 1088 + r * 68 + c0);
            float z0 = zA.x + zB.x, z1 = zA.y + zB.y, z2 = zA.z + zB.z, z3 = zA.w + zB.w;
            float s = hred(z0 + z1 + z2 + z3);
            float qq = hred(z0 * z0 + z1 * z1 + z2 * z2 + z3 * z3);
            float m = s * (1.f / 64.f);
            float rstd = rsqrtf(qq * (1.f / 64.f) - m * m + EPSV);
            float xh0 = (z0 - m) * rstd, xh1 = (z1 - m) * rstd;
            float xh2 = (z2 - m) * rstd, xh3 = (z3 - m) * rstd;
            float gx0 = (gv0 * xh0 + bv0 - t4c.x) * gv0;
            float gx1 = (gv1 * xh1 + bv1 - t4c.y) * gv1;
            float gx2 = (gv2 * xh2 + bv2 - t4c.z) * gv2;
            float gx3 = (gv3 * xh3 + bv3 - t4c.w) * gv3;
            float s1 = hred(gx0 + gx1 + gx2 + gx3);
            float s2 = hred(gx0 * xh0 + gx1 * xh1 + gx2 * xh2 + gx3 * xh3);
            float sc = rstd * (1.f / 64.f);
            float4 gr;
            gr.x = (64.f * gx0 - s1 - xh0 * s2) * sc;
            gr.y = (64.f * gx1 - s1 - xh1 * s2) * sc;
            gr.z = (64.f * gx2 - s1 - xh2 * s2) * sc;
            gr.w = (64.f * gx3 - s1 - xh3 * s2) * sc;
            *(float4*)(sG + r * 68 + c0) = gr;
        } else {
            // Cf[i=r][m=cg] = toki[i]*lr[m]*(XQ[i].XK[m] + 1) for m<=i
            float cf = 0.f;
            if (cg <= r) {
                unsigned long long acc = 0ULL;
#pragma unroll 8
                for (int kk = 0; kk < 32; kk++) {
                    unsigned long long a = *(const unsigned long long*)(sXQ + r * 68 + 2 * kk);
                    unsigned long long bb = *(const unsigned long long*)(sXK + cg * 68 + 2 * kk);
                    fma2(acc, a, bb);
                }
                float2 p = up2(acc);
                cf = tokir * lr[cg] * (p.x + p.y + 1.f);
            }
            Cf[r * 16 + cg] = cf;
        }
        __syncthreads();                                   // (C)

        if (t0) {
            // Z1_bar = ZQ - Cf@grad ; out = XQ + ln_fwd(Z1_bar)
            float4 yA = *(const float4*)(sPQ + r * 68 + c0);
            float4 yB = *(const float4*)(sPQ + 1088 + r * 68 + c0);
            unsigned long long y01 = pk2(yA.x + yB.x, yA.y + yB.y);
            unsigned long long y23 = pk2(yA.z + yB.z, yA.w + yB.w);
#pragma unroll
            for (int mm = 0; mm < 16; mm++) {
                float nc = -Cf[r * 16 + mm];
                unsigned long long pc = pk2(nc, nc);
                ulonglong2 g = *(const ulonglong2*)(sG + mm * 68 + c0);
                fma2(y01, pc, g.x); fma2(y23, pc, g.y);
            }
            float2 pA = up2(y01), pB = up2(y23);
            float y0 = pA.x, y1 = pA.y, y2 = pB.x, y3 = pB.y;
            float s = hred(y0 + y1 + y2 + y3);
            float qq = hred(y0 * y0 + y1 * y1 + y2 * y2 + y3 * y3);
            float m = s * (1.f / 64.f);
            float rstd = rsqrtf(qq * (1.f / 64.f) - m * m + EPSV);
            float4 o;
            o.x = q4c.x + gv0 * ((y0 - m) * rstd) + bv0;
            o.y = q4c.y + gv1 * ((y1 - m) * rstd) + bv1;
            o.z = q4c.z + gv2 * ((y2 - m) * rstd) + bv2;
            o.w = q4c.w + gv3 * ((y3 - m) * rstd) + bv3;
            *(float4*)(g_ttt + gb2 + (size_t)(nb * MBm + r) * WID) = o;
        } else {
            // W1 -= XK^T @ (lrw*G); b1 -= col sums
            const int d = t & 63;
            const int kbase = (t >> 6) * 16;
            float gvv[16];
            float bs = 0.f;
#pragma unroll
            for (int mm = 0; mm < 16; mm++) {
                gvv[mm] = lrw[mm] * sG[mm * 68 + d];
                bs += gvv[mm];
            }
            unsigned long long acc[8];
#pragma unroll
            for (int j = 0; j < 8; j++) acc[j] = 0ULL;
#pragma unroll
            for (int mm = 0; mm < 16; mm++) {
                unsigned long long gp = pk2(gvv[mm], gvv[mm]);
                ulonglong2 xx0 = *(const ulonglong2*)(sXK + mm * 68 + kbase);
                ulonglong2 xx1 = *(const ulonglong2*)(sXK + mm * 68 + kbase + 4);
                ulonglong2 xx2 = *(const ulonglong2*)(sXK + mm * 68 + kbase + 8);
                ulonglong2 xx3 = *(const ulonglong2*)(sXK + mm * 68 + kbase + 12);
                fma2(acc[0], gp, xx0.x); fma2(acc[1], gp, xx0.y);
                fma2(acc[2], gp, xx1.x); fma2(acc[3], gp, xx1.y);
                fma2(acc[4], gp, xx2.x); fma2(acc[5], gp, xx2.y);
                fma2(acc[6], gp, xx3.x); fma2(acc[7], gp, xx3.y);
            }
#pragma unroll
            for (int j = 0; j < 8; j++) {
                float2 p = up2(acc[j]);
                int k0 = kbase + 2 * j;
                W1s[k0 * 64 + d]       -= p.x;
                W1s[(k0 + 1) * 64 + d] -= p.y;
            }
            if (t < 64) b1s[t] -= bs;
        }
    }
}

// ------------------------- post: t = gelu(gate) * LN(out) -> bf16 hi/lo -----
__global__ __launch_bounds__(256) void postfuse_kernel(
    const float* __restrict__ pns, const float* __restrict__ pnb)
{
    __shared__ float ws[8], wq2[8];
    __shared__ float smu, srs;
    const int row = blockIdx.x;
    const int tid = threadIdx.x;
    const int lane = tid & 31, wid = tid >> 5;
    const float* o = g_ttt + (size_t)row * WID;
    const float* gp = g_gate + (size_t)row * WID;

    float v[3], s = 0.f, q = 0.f;
#pragma unroll
    for (int i = 0; i < 3; i++) {
        v[i] = o[tid + i * 256];
        s += v[i]; q += v[i] * v[i];
    }
    s = wred(s); q = wred(q);
    if (lane == 0) { ws[wid] = s; wq2[wid] = q; }
    __syncthreads();
    if (tid == 0) {
        float S = 0.f, Q = 0.f;
#pragma unroll
        for (int i = 0; i < 8; i++) { S += ws[i]; Q += wq2[i]; }
        float m = S * (1.f / 768.f);
        smu = m;
        srs = rsqrtf(Q * (1.f / 768.f) - m * m + EPSV);
    }
    __syncthreads();
    const float m = smu, rs = srs;
#pragma unroll
    for (int i = 0; i < 3; i++) {
        int c = tid + i * 256;
        float z = pns[c] * ((v[i] - m) * rs) + pnb[c];
        float x = gp[c];
        float gl = 0.5f * x * (1.f + tanhf(0.7978845608028654f * (x + 0.044715f * x * x * x)));
        float val = gl * z;
        __nv_bfloat16 hi = __float2bfloat16(val);
        g_th[(size_t)row * WID + c] = hi;
        g_tl[(size_t)row * WID + c] = __float2bfloat16(val - __bfloat162float(hi));
    }
}

// ------------------------- launch --------------------------------------------
extern "C" void kernel_launch(void* const* d_in, const int* in_sizes, int n_in,
                              void* d_out, int out_size)
{
    const float* hidden = (const float*)d_in[0];
    const float* wq  = (const float*)d_in[1];
    const float* wv  = (const float*)d_in[2];
    const float* wo  = (const float*)d_in[3];
    const float* wg  = (const float*)d_in[4];
    const float* cqk = (const float*)d_in[5];
    const float* cqb = (const float*)d_in[6];
    const float* ckk = (const float*)d_in[7];
    const float* ckb = (const float*)d_in[8];
    const float* W1  = (const float*)d_in[9];
    const float* b1  = (const float*)d_in[10];
    const float* tns = (const float*)d_in[11];
    const float* tnb = (const float*)d_in[12];
    const float* lrk = (const float*)d_in[13];
    const float* lrb = (const float*)d_in[14];
    const float* lti = (const float*)d_in[15];
    const float* pns = (const float*)d_in[16];
    const float* pnb = (const float*)d_in[17];
    float* out = (float*)d_out;

    float *p_xqk, *p_xv, *p_gate;
    __nv_bfloat16 *p_hh, *p_hl, *p_th, *p_tl, *p_wt;
    cudaGetSymbolAddress((void**)&p_xqk,  g_xqk);
    cudaGetSymbolAddress((void**)&p_xv,   g_xv);
    cudaGetSymbolAddress((void**)&p_gate, g_gate);
    cudaGetSymbolAddress((void**)&p_hh,   g_hh);
    cudaGetSymbolAddress((void**)&p_hl,   g_hl);
    cudaGetSymbolAddress((void**)&p_th,   g_th);
    cudaGetSymbolAddress((void**)&p_tl,   g_tl);
    cudaGetSymbolAddress((void**)&p_wt,   g_wt);

    const int smem_mma = 2 * STAGEB;
    cudaFuncSetAttribute(mma_gemm_kernel, cudaFuncAttributeMaxDynamicSharedMemorySize, smem_mma);

    // 1: lr + weight cvt fused
    prep_kernel<<<2048 + 4 * 576, 256>>>(hidden, lrk, lrb, wq, wv, wg, wo);
    // 2: hidden hi/lo split
    cvt_hilo_kernel<<<(MTOT * WID / 4 + 255) / 256, 256>>>(hidden, p_hh, p_hl, MTOT * WID / 4);
    // 3: fused QVG GEMM
    {
        dim3 gg(18, MTOT / 128);
        mma_gemm_kernel<<<gg, 256, smem_mma>>>(p_hh, p_hl, p_wt, p_wt + (size_t)3 * WW,
                                               p_xqk, p_xv, p_gate);
    }
    // 4: scan (fused conv+rope)  — profiled launch
    ttt_scan_kernel<<<Bsz * NH, 512>>>(W1, b1, tns, tnb, lti, cqk, cqb, ckk, ckb);
    // 5: post LN * gelu gate
    postfuse_kernel<<<MTOT, 256>>>(pns, pnb);
    // 6: output GEMM
    {
        dim3 gg(6, MTOT / 128);
        mma_gemm_kernel<<<gg, 256, smem_mma>>>(p_th, p_tl, p_wt + (size_t)6 * WW, p_wt + (size_t)7 * WW,
                                               out, out, out);
    }
}